// round 15
// baseline (speedup 1.0000x reference)
#include <cuda_runtime.h>

// LSTM_46316927320185 — R15: gate-split lanes — warp = 1 elem, 2 gates/lane
// B=4096, T=512, EMB=32, HID=16, VOCAB=50000.
//
// R13 taught: dummy work isn't free (divergence doesn't refund issue slots);
// 2-elems/lane can't hit 7 elems/SMSP without waste. R15 doubles warp count
// instead: warp = ONE elem; lane (gp=lane>>4, j=lane&15) computes 2 gates
// (gp0: i,f; gp1: g,o) for unit j over full K. Output-dim split => NO
// accumulator merge (R8's failure); only activated gate VALUES cross halves:
// 2 shfl_xor(16) + 2 FSEL; c,h computed redundantly (bitwise identical).
// 4096 warps -> 148 CTAs x 896thr = exactly 7 warps/SMSP, even, 1.2% tail.
// xc folded into accumulator init (pack2) -> FMA-pipe ~23 ops/elem-step.
// Table phase unchanged: 12.8MB gate-preactivation table (i,f,o pre-halved).

#define HID    16
#define EMB    32
#define T_LEN  512
#define BATCH  4096
#define VOCAB  50000

typedef unsigned long long u64;

// [v*HID + j] -> float4 (xp_i/2, xp_f/2, xp_g, xp_o/2), biases folded. 12.8 MB.
__device__ float4 g_tbl[(size_t)VOCAB * HID];

__device__ __forceinline__ u64 fma2(u64 a, u64 b, u64 c) {
    u64 d; asm("fma.rn.f32x2 %0, %1, %2, %3;" : "=l"(d) : "l"(a), "l"(b), "l"(c)); return d;
}
__device__ __forceinline__ u64 mul2(u64 a, u64 b) {
    u64 d; asm("mul.rn.f32x2 %0, %1, %2;" : "=l"(d) : "l"(a), "l"(b)); return d;
}
__device__ __forceinline__ u64 rep2(float v) {
    u64 r; asm("mov.b64 %0, {%1, %1};" : "=l"(r) : "f"(v)); return r;
}
__device__ __forceinline__ u64 pack2(float a, float b) {
    u64 r; asm("mov.b64 %0, {%1, %2};" : "=l"(r) : "f"(a), "f"(b)); return r;
}
__device__ __forceinline__ void unpack2(u64 v, float& lo, float& hi) {
    asm("mov.b64 {%0, %1}, %2;" : "=f"(lo), "=f"(hi) : "l"(v));
}
__device__ __forceinline__ float hadd2(u64 v) {
    float lo, hi; unpack2(v, lo, hi); return lo + hi;
}
__device__ __forceinline__ float tanh_ap(float x) {
    float y; asm("tanh.approx.f32 %0, %1;" : "=f"(y) : "f"(x)); return y;
}

// ============ Phase A: per-vocab projection table ============
#define PT_THREADS 256
#define PT_GRID    ((VOCAB * HID) / PT_THREADS)   // 3125

__global__ __launch_bounds__(PT_THREADS)
void proj_table_kernel(const float* __restrict__ embed,
                       const float* __restrict__ w_ih,
                       const float* __restrict__ b_ih,
                       const float* __restrict__ b_hh)
{
    // gate-packed transposed weights: [k*HID+j] = ((wi,wf),(wg,wo))
    __shared__ ulonglong2 w_u[EMB * HID];   // 8 KB

    const int tid = threadIdx.x;
    for (int i = tid; i < EMB * HID; i += PT_THREADS) {
        int k = i / HID, jj = i % HID;
        float4 w = make_float4(w_ih[(0 * HID + jj) * EMB + k],
                               w_ih[(1 * HID + jj) * EMB + k],
                               w_ih[(2 * HID + jj) * EMB + k],
                               w_ih[(3 * HID + jj) * EMB + k]);
        *(float4*)&w_u[i] = w;
    }
    __syncthreads();

    const int gid = blockIdx.x * PT_THREADS + tid;
    const int v = gid >> 4;        // vocab row
    const int j = gid & 15;        // hidden unit

    const float4* er4 = (const float4*)(embed + (size_t)v * EMB);
    u64 a01 = 0ull, a23 = 0ull;
    #pragma unroll
    for (int c4 = 0; c4 < 8; ++c4) {
        const float4 ev = er4[c4];              // LDG.128, broadcast across j-lanes
        u64 q;
        q = rep2(ev.x);
        { const ulonglong2 w = w_u[(c4 * 4 + 0) * HID + j];
          a01 = fma2(q, w.x, a01); a23 = fma2(q, w.y, a23); }
        q = rep2(ev.y);
        { const ulonglong2 w = w_u[(c4 * 4 + 1) * HID + j];
          a01 = fma2(q, w.x, a01); a23 = fma2(q, w.y, a23); }
        q = rep2(ev.z);
        { const ulonglong2 w = w_u[(c4 * 4 + 2) * HID + j];
          a01 = fma2(q, w.x, a01); a23 = fma2(q, w.y, a23); }
        q = rep2(ev.w);
        { const ulonglong2 w = w_u[(c4 * 4 + 3) * HID + j];
          a01 = fma2(q, w.x, a01); a23 = fma2(q, w.y, a23); }
    }
    float ai, af, ag, ao;
    unpack2(a01, ai, af);
    unpack2(a23, ag, ao);
    // gates i,f,o pre-scaled by 0.5 (sigmoid identity); g unscaled (tanh)
    g_tbl[gid] = make_float4(0.5f * (ai + b_ih[j]           + b_hh[j]),
                             0.5f * (af + b_ih[HID + j]     + b_hh[HID + j]),
                                     ag + b_ih[2 * HID + j] + b_hh[2 * HID + j],
                             0.5f * (ao + b_ih[3 * HID + j] + b_hh[3 * HID + j]));
}

// ============ Phase B: recurrence — warp = 1 elem, 2 gates per lane ============
#define RC_WARPS   28
#define RC_THREADS 896                 // 28 warps -> exactly 7 per SMSP (even)
#define RC_EPC     28                  // 1 elem per warp
#define RC_GRID    148                 // 148*28 = 4144 >= 4096 (tail masked)

__global__ __launch_bounds__(RC_THREADS, 1)
void recur_kernel(const int*   __restrict__ x,
                  const float* __restrict__ w_hh,
                  const float* __restrict__ fc_w,
                  const float* __restrict__ fc_b,
                  float*       __restrict__ out)
{
    // double-buffered h staging: [buf][warp(=elem)][j]  (3.5 KB)
    __shared__ float h_s[2][RC_WARPS][HID];

    const int tid  = threadIdx.x;
    const int warp = tid >> 5, lane = tid & 31;
    const int gp   = lane >> 4;          // gate half: gp0 -> (i,f), gp1 -> (g,o)
    const int j    = lane & 15;          // hidden unit owned
    const int b    = blockIdx.x * RC_EPC + warp;
    const int bc   = (b < BATCH) ? b : (BATCH - 1);   // clamp (store masked)

    // this half's two gate rows of w_hh, K-pair packed.
    // gate a = gp*2 (i or g), gate b = gp*2+1 (f or o).
    // sigmoid-fold: halve rows for gates i,f,o (all except g = gate 2).
    u64 wka[8], wkb[8];
    {
        const u64* wra = (const u64*)(w_hh + (size_t)((gp * 2 + 0) * HID + j) * HID);
        const u64* wrb = (const u64*)(w_hh + (size_t)((gp * 2 + 1) * HID + j) * HID);
        #pragma unroll
        for (int i = 0; i < 8; ++i) { wka[i] = wra[i]; wkb[i] = wrb[i]; }
        const u64 hlf = rep2(0.5f);
        if (gp == 0) {                       // gates i,f both halve
            #pragma unroll
            for (int i = 0; i < 8; ++i) { wka[i] = mul2(wka[i], hlf); wkb[i] = mul2(wkb[i], hlf); }
        } else {                             // gate g unscaled, gate o halves
            #pragma unroll
            for (int i = 0; i < 8; ++i) { wkb[i] = mul2(wkb[i], hlf); }
        }
    }
    // activation constants: gate a is sigmoid on gp0 (i), tanh on gp1 (g)
    const float ka = gp ? 1.0f : 0.5f;
    const float ca = gp ? 0.0f : 0.5f;

    const int* xcol = x + (size_t)bc * T_LEN;

    // gather pipeline: own 2 gates' xp (float2) for t (xc), t+1 (xn); idx t+2
    const float* tb = (const float*)g_tbl;
    #define XP_LD(vi) (*(const float2*)(tb + ((size_t)(vi) * HID + j) * 4 + gp * 2))
    float2 xc = XP_LD(xcol[0]);
    float2 xn = XP_LD(xcol[1]);
    int    i2 = xcol[2];

    float h = 0.f, c = 0.f;

    #pragma unroll 2
    for (int t = 0; t < T_LEN; ++t) {
        const int buf = t & 1;
        if (gp == 0) h_s[buf][warp][j] = h;   // halves hold identical h
        __syncwarp();

        // kick next gathers early (t+2 row; t+3 index)
        const int    tn = (t + 3 < T_LEN) ? (t + 3) : (T_LEN - 1);
        const float2 x2 = XP_LD(i2);
        const int    i3 = xcol[tn];

        // own elem's 16 h values as 4 ready-packed u64 (broadcast LDS)
        const ulonglong2* hp = (const ulonglong2*)h_s[buf][warp];
        u64 a0 = pack2(xc.x, 0.f);            // xp folded into init
        u64 a1 = pack2(xc.y, 0.f);
        #pragma unroll
        for (int i = 0; i < 4; ++i) {
            const ulonglong2 hv = hp[i];
            a0 = fma2(hv.x, wka[2 * i], a0); a0 = fma2(hv.y, wka[2 * i + 1], a0);
            a1 = fma2(hv.x, wkb[2 * i], a1); a1 = fma2(hv.y, wkb[2 * i + 1], a1);
        }
        const float sa = hadd2(a0);           // gate a preact (scaled if sigmoid)
        const float sb = hadd2(a1);           // gate b preact

        xc = xn; xn = x2; i2 = i3;

        // activate own gates: va = ig (gp0) / gg (gp1); vb = fg (gp0) / og (gp1)
        const float va = fmaf(tanh_ap(sa), ka, ca);
        const float vb = fmaf(tanh_ap(sb), 0.5f, 0.5f);

        // exchange with partner half
        const float o1 = __shfl_xor_sync(0xffffffffu, va, 16);  // gg / ig
        const float o2 = __shfl_xor_sync(0xffffffffu, vb, 16);  // og / fg

        const float prod = va * o1;           // ig*gg (commutative, both sides)
        const float fg   = gp ? o2 : vb;
        const float og   = gp ? vb : o2;
        c = fmaf(fg, c, prod);
        h = og * tanh_ap(c);                  // identical on both halves
    }

    // FC head: reduce over j within this 16-lane half (both halves identical)
    float v = h * fc_w[j];
    v += __shfl_xor_sync(0xffffffffu, v, 8);
    v += __shfl_xor_sync(0xffffffffu, v, 4);
    v += __shfl_xor_sync(0xffffffffu, v, 2);
    v += __shfl_xor_sync(0xffffffffu, v, 1);
    if (lane == 0 && b < BATCH)
        out[b] = fmaf(tanh_ap(0.5f * (v + fc_b[0])), 0.5f, 0.5f);
    #undef XP_LD
}

extern "C" void kernel_launch(void* const* d_in, const int* in_sizes, int n_in,
                              void* d_out, int out_size)
{
    const int*   x     = (const int*)  d_in[0];
    const float* embed = (const float*)d_in[1];
    const float* w_ih  = (const float*)d_in[2];
    const float* w_hh  = (const float*)d_in[3];
    const float* b_ih  = (const float*)d_in[4];
    const float* b_hh  = (const float*)d_in[5];
    const float* fc_w  = (const float*)d_in[6];
    const float* fc_b  = (const float*)d_in[7];
    float* out = (float*)d_out;

    proj_table_kernel<<<PT_GRID, PT_THREADS>>>(embed, w_ih, b_ih, b_hh);
    recur_kernel<<<RC_GRID, RC_THREADS>>>(x, w_hh, fc_w, fc_b, out);
}

// round 16
// speedup vs baseline: 1.1083x; 1.1083x over previous
#include <cuda_runtime.h>

// LSTM_46316927320185 — R16: R9 skeleton (proven optimum) + xc-fold + int4 index buffer
// B=4096, T=512, EMB=32, HID=16, VOCAB=50000.
//
// R11/R13/R15 all lost to R9's mapping (warp = 2 elems, full-K per lane, smem
// h-broadcast, zero merge ops; 148 CTAs x 14 warps = 4/4/3/3 per SMSP).
// R16 keeps that skeleton verbatim and trims measured waste inside the step:
//  (1) xc folded into accumulator init via pack2 -> -4 FADD/elem on FMA pipe
//  (2) indices buffered as int4: 1 LDG.128 / 4 steps replaces per-step
//      LDG.32 + SEL clamp (pipeline: i3(t) = cur.w | nxt.x|y|z by ts)
//  (3) tb-outer / ts-inner x4 loop amortizes loop arithmetic.
// Table phase unchanged: 12.8MB gate-preactivation table (i,f,o pre-halved).

#define HID    16
#define EMB    32
#define T_LEN  512
#define BATCH  4096
#define VOCAB  50000

typedef unsigned long long u64;

// [v*HID + j] -> float4 (xp_i/2, xp_f/2, xp_g, xp_o/2), biases folded. 12.8 MB.
__device__ float4 g_tbl[(size_t)VOCAB * HID];

__device__ __forceinline__ u64 fma2(u64 a, u64 b, u64 c) {
    u64 d; asm("fma.rn.f32x2 %0, %1, %2, %3;" : "=l"(d) : "l"(a), "l"(b), "l"(c)); return d;
}
__device__ __forceinline__ u64 mul2(u64 a, u64 b) {
    u64 d; asm("mul.rn.f32x2 %0, %1, %2;" : "=l"(d) : "l"(a), "l"(b)); return d;
}
__device__ __forceinline__ u64 rep2(float v) {
    u64 r; asm("mov.b64 %0, {%1, %1};" : "=l"(r) : "f"(v)); return r;
}
__device__ __forceinline__ u64 pack2(float a, float b) {
    u64 r; asm("mov.b64 %0, {%1, %2};" : "=l"(r) : "f"(a), "f"(b)); return r;
}
__device__ __forceinline__ void unpack2(u64 v, float& lo, float& hi) {
    asm("mov.b64 {%0, %1}, %2;" : "=f"(lo), "=f"(hi) : "l"(v));
}
__device__ __forceinline__ float hadd2(u64 v) {
    float lo, hi; unpack2(v, lo, hi); return lo + hi;
}
__device__ __forceinline__ float tanh_ap(float x) {
    float y; asm("tanh.approx.f32 %0, %1;" : "=f"(y) : "f"(x)); return y;
}

// ============ Phase A: per-vocab projection table ============
#define PT_THREADS 256
#define PT_GRID    ((VOCAB * HID) / PT_THREADS)   // 3125

__global__ __launch_bounds__(PT_THREADS)
void proj_table_kernel(const float* __restrict__ embed,
                       const float* __restrict__ w_ih,
                       const float* __restrict__ b_ih,
                       const float* __restrict__ b_hh)
{
    // gate-packed transposed weights: [k*HID+j] = ((wi,wf),(wg,wo))
    __shared__ ulonglong2 w_u[EMB * HID];   // 8 KB

    const int tid = threadIdx.x;
    for (int i = tid; i < EMB * HID; i += PT_THREADS) {
        int k = i / HID, jj = i % HID;
        float4 w = make_float4(w_ih[(0 * HID + jj) * EMB + k],
                               w_ih[(1 * HID + jj) * EMB + k],
                               w_ih[(2 * HID + jj) * EMB + k],
                               w_ih[(3 * HID + jj) * EMB + k]);
        *(float4*)&w_u[i] = w;
    }
    __syncthreads();

    const int gid = blockIdx.x * PT_THREADS + tid;
    const int v = gid >> 4;        // vocab row
    const int j = gid & 15;        // hidden unit

    const float4* er4 = (const float4*)(embed + (size_t)v * EMB);
    u64 a01 = 0ull, a23 = 0ull;
    #pragma unroll
    for (int c4 = 0; c4 < 8; ++c4) {
        const float4 ev = er4[c4];              // LDG.128, broadcast across j-lanes
        u64 q;
        q = rep2(ev.x);
        { const ulonglong2 w = w_u[(c4 * 4 + 0) * HID + j];
          a01 = fma2(q, w.x, a01); a23 = fma2(q, w.y, a23); }
        q = rep2(ev.y);
        { const ulonglong2 w = w_u[(c4 * 4 + 1) * HID + j];
          a01 = fma2(q, w.x, a01); a23 = fma2(q, w.y, a23); }
        q = rep2(ev.z);
        { const ulonglong2 w = w_u[(c4 * 4 + 2) * HID + j];
          a01 = fma2(q, w.x, a01); a23 = fma2(q, w.y, a23); }
        q = rep2(ev.w);
        { const ulonglong2 w = w_u[(c4 * 4 + 3) * HID + j];
          a01 = fma2(q, w.x, a01); a23 = fma2(q, w.y, a23); }
    }
    float ai, af, ag, ao;
    unpack2(a01, ai, af);
    unpack2(a23, ag, ao);
    // gates i,f,o pre-scaled by 0.5 (sigmoid identity); g unscaled (tanh)
    g_tbl[gid] = make_float4(0.5f * (ai + b_ih[j]           + b_hh[j]),
                             0.5f * (af + b_ih[HID + j]     + b_hh[HID + j]),
                                     ag + b_ih[2 * HID + j] + b_hh[2 * HID + j],
                             0.5f * (ao + b_ih[3 * HID + j] + b_hh[3 * HID + j]));
}

// ============ Phase B: recurrence — warp = 2 elems, full-K, uniform grid ============
#define RC_WARPS   14
#define RC_THREADS 448                 // 14 warps -> exactly 1 CTA per SM
#define RC_EPC     28                  // 2 elems per warp
#define RC_GRID    148                 // 148*28 = 4144 >= 4096 (tail clamped)
#define T_BLKS     (T_LEN / 4)         // 128

__global__ __launch_bounds__(RC_THREADS, 1)
void recur_kernel(const int*   __restrict__ x,
                  const float* __restrict__ w_hh,
                  const float* __restrict__ fc_w,
                  const float* __restrict__ fc_b,
                  float*       __restrict__ out)
{
    // double-buffered h staging: [buf][warp][elem][j] (j-pairs contiguous -> u64)
    __shared__ float h_s[2][RC_WARPS][2][HID];

    const int tid  = threadIdx.x;
    const int warp = tid >> 5, lane = tid & 31;
    const int eh   = lane >> 4;          // which of the warp's 2 elems
    const int j    = lane & 15;          // hidden unit owned
    const int b    = blockIdx.x * RC_EPC + warp * 2 + eh;
    const int bc   = (b < BATCH) ? b : (BATCH - 1);   // clamp (store masked)

    // K-pair packed recurrent weights: wk[g][i] = (w[g,j,2i], w[g,j,2i+1]);
    // gates i,f,o halved once here (sigmoid scale folding).
    u64 wk[4][8];
    #pragma unroll
    for (int g = 0; g < 4; ++g) {
        const u64* wr = (const u64*)(w_hh + (size_t)(g * HID + j) * HID);
        #pragma unroll
        for (int i = 0; i < 8; ++i) wk[g][i] = wr[i];
    }
    {
        const u64 hlf = rep2(0.5f);
        #pragma unroll
        for (int i = 0; i < 8; ++i) {
            wk[0][i] = mul2(wk[0][i], hlf);
            wk[1][i] = mul2(wk[1][i], hlf);
            wk[3][i] = mul2(wk[3][i], hlf);
        }
    }

    // indices as int4 blocks (x rows are 2KB-aligned; LDG.128 broadcast per group)
    const int4* xcol4 = (const int4*)(x + (size_t)bc * T_LEN);

    int4 cur = xcol4[0];                            // idx[0..3]
    float4 xc = g_tbl[(size_t)cur.x * HID + j];     // row for t
    float4 xn = g_tbl[(size_t)cur.y * HID + j];     // row for t+1
    int    i2 = cur.z;                              // index for t+2

    float h = 0.f, c = 0.f;

    for (int tb = 0; tb < T_BLKS; ++tb) {
        const int4 nxt = xcol4[(tb + 1 < T_BLKS) ? (tb + 1) : (T_BLKS - 1)];
        #pragma unroll
        for (int ts = 0; ts < 4; ++ts) {
            const int buf = ts & 1;                 // t = 4*tb+ts, 4|4tb
            h_s[buf][warp][eh][j] = h;
            __syncwarp();

            // kick next gather early (row t+2); index t+3 from buffered blocks
            const float4 x2 = g_tbl[(size_t)i2 * HID + j];
            const int    i3 = (ts == 0) ? cur.w
                            : (ts == 1) ? nxt.x
                            : (ts == 2) ? nxt.y : nxt.z;

            // own elem's 16 h values as 4 ready-packed ulonglong2 (broadcast LDS)
            const ulonglong2* hp = (const ulonglong2*)h_s[buf][warp][eh];
            // xp folded into accumulator init (ALU movs; -4 FADD on fma pipe)
            u64 a0 = pack2(xc.x, 0.f);
            u64 a1 = pack2(xc.y, 0.f);
            u64 a2 = pack2(xc.z, 0.f);
            u64 a3 = pack2(xc.w, 0.f);
            #pragma unroll
            for (int i = 0; i < 4; ++i) {
                const ulonglong2 hv = hp[i];
                a0 = fma2(hv.x, wk[0][2 * i], a0); a0 = fma2(hv.y, wk[0][2 * i + 1], a0);
                a1 = fma2(hv.x, wk[1][2 * i], a1); a1 = fma2(hv.y, wk[1][2 * i + 1], a1);
                a2 = fma2(hv.x, wk[2][2 * i], a2); a2 = fma2(hv.y, wk[2][2 * i + 1], a2);
                a3 = fma2(hv.x, wk[3][2 * i], a3); a3 = fma2(hv.y, wk[3][2 * i + 1], a3);
            }
            const float si = hadd2(a0);   // xp included; i,f,o pre-scaled by 0.5
            const float sf = hadd2(a1);
            const float sg = hadd2(a2);   // unscaled (tanh gate)
            const float so = hadd2(a3);

            xc = xn; xn = x2; i2 = i3;

            const float ig = fmaf(tanh_ap(si), 0.5f, 0.5f);
            const float fg = fmaf(tanh_ap(sf), 0.5f, 0.5f);
            const float gg = tanh_ap(sg);
            const float og = fmaf(tanh_ap(so), 0.5f, 0.5f);
            c = fg * c + ig * gg;
            h = og * tanh_ap(c);
        }
        cur = nxt;
    }

    // FC head: reduce over j within this elem's 16-lane half
    float v = h * fc_w[j];
    v += __shfl_xor_sync(0xffffffffu, v, 8);
    v += __shfl_xor_sync(0xffffffffu, v, 4);
    v += __shfl_xor_sync(0xffffffffu, v, 2);
    v += __shfl_xor_sync(0xffffffffu, v, 1);
    if (j == 0 && b < BATCH)
        out[b] = fmaf(tanh_ap(0.5f * (v + fc_b[0])), 0.5f, 0.5f);
}

extern "C" void kernel_launch(void* const* d_in, const int* in_sizes, int n_in,
                              void* d_out, int out_size)
{
    const int*   x     = (const int*)  d_in[0];
    const float* embed = (const float*)d_in[1];
    const float* w_ih  = (const float*)d_in[2];
    const float* w_hh  = (const float*)d_in[3];
    const float* b_ih  = (const float*)d_in[4];
    const float* b_hh  = (const float*)d_in[5];
    const float* fc_w  = (const float*)d_in[6];
    const float* fc_b  = (const float*)d_in[7];
    float* out = (float*)d_out;

    proj_table_kernel<<<PT_GRID, PT_THREADS>>>(embed, w_ih, b_ih, b_hh);
    recur_kernel<<<RC_GRID, RC_THREADS>>>(x, w_hh, fc_w, fc_b, out);
}